// round 1
// baseline (speedup 1.0000x reference)
#include <cuda_runtime.h>
#include <math.h>

#define NE    8
#define HDIM  1024
#define IDIM  4096
#define NTOK  4096
#define CAP   4096
#define NASSIGN (NTOK * 2)

// ---------------- scratch (static device globals; no runtime alloc) ----------
__device__ float g_Xg[33554432];      // [NE*CAP, HDIM] gathered activations (128MB)
__device__ float g_Hbuf[134217728];   // [NE*CAP, IDIM] silu(X@w1)*(X@w3)     (512MB)
__device__ float g_Y[33554432];       // [NE*CAP, HDIM] expert outputs        (128MB)
__device__ int   g_cnt[NE];           // per-expert row counts
__device__ int   g_sel[NASSIGN];      // per-assignment expert id
__device__ float g_wgt[NASSIGN];      // per-assignment combine weight
__device__ int   g_slotOf[NASSIGN];   // assignment -> row slot in expert segment

// ---------------- kernel 0: zero counters ------------------------------------
__global__ void zero_cnt_kernel() {
    if (threadIdx.x < NE) g_cnt[threadIdx.x] = 0;
}

// ---------------- kernel 1: router (logits, top-2, softmax) ------------------
// one block per token; 8 warps, warp w computes logit for expert w
__global__ void router_kernel(const float* __restrict__ X,
                              const float* __restrict__ GW,
                              float* __restrict__ out_logits) {
    int t = blockIdx.x;
    int w = threadIdx.x >> 5;
    int lane = threadIdx.x & 31;
    __shared__ float slog[NE];

    const float* x = X + (size_t)t * HDIM;
    float acc = 0.f;
    for (int i = lane; i < HDIM; i += 32)
        acc += x[i] * GW[i * NE + w];
    #pragma unroll
    for (int o = 16; o > 0; o >>= 1)
        acc += __shfl_xor_sync(0xffffffffu, acc, o);
    if (lane == 0) {
        slog[w] = acc;
        out_logits[t * NE + w] = acc;
    }
    __syncthreads();

    if (threadIdx.x == 0) {
        // top-2 with lax.top_k tie semantics (lower index wins on ties)
        int i0 = 0; float l0 = slog[0];
        #pragma unroll
        for (int e = 1; e < NE; e++)
            if (slog[e] > l0) { l0 = slog[e]; i0 = e; }
        int i1 = -1; float l1 = -1e30f;
        #pragma unroll
        for (int e = 0; e < NE; e++)
            if (e != i0 && slog[e] > l1) { l1 = slog[e]; i1 = e; }
        // softmax over the two selected logits (l0 >= l1)
        float e1 = expf(l1 - l0);
        float inv = 1.f / (1.f + e1);
        g_sel[2 * t]     = i0;  g_wgt[2 * t]     = inv;
        g_sel[2 * t + 1] = i1;  g_wgt[2 * t + 1] = e1 * inv;
    }
}

// ---------------- kernel 2: scatter (assign slots) ---------------------------
__global__ void scatter_kernel() {
    int idx = blockIdx.x * blockDim.x + threadIdx.x;   // assignment id
    if (idx >= NASSIGN) return;
    int e = g_sel[idx];
    int pos = atomicAdd(&g_cnt[e], 1);
    g_slotOf[idx] = e * CAP + pos;
}

// ---------------- kernel 3: gather activation rows ---------------------------
// one block per assignment; copy token row into its slot (float4)
__global__ void gather_kernel(const float* __restrict__ X) {
    int a = blockIdx.x;
    int slot = g_slotOf[a];
    int t = a >> 1;
    const float4* src = (const float4*)(X + (size_t)t * HDIM);
    float4* dst = (float4*)(g_Xg + (size_t)slot * HDIM);
    dst[threadIdx.x] = src[threadIdx.x];   // 256 threads * 4 = 1024 floats
}

// ---------------- kernel 4: fused GEMM1 (w1 & w3 + SiLU*mul) ----------------
// C[128 x 64] tiles, dual accumulators; grid.x = IDIM/64, grid.y = NE*32
__global__ __launch_bounds__(256) void gemm1_kernel(const float* __restrict__ W1,
                                                    const float* __restrict__ W3) {
    int e  = blockIdx.y >> 5;
    int mt = blockIdx.y & 31;
    int cnt = g_cnt[e];
    int row0 = mt * 128;
    if (row0 >= cnt) return;

    const float* A  = g_Xg + (size_t)(e * CAP + row0) * HDIM;
    const float* B1 = W1 + (size_t)e * HDIM * IDIM + blockIdx.x * 64;
    const float* B3 = W3 + (size_t)e * HDIM * IDIM + blockIdx.x * 64;

    __shared__ float As[16][132];
    __shared__ float Bs1[16][68];
    __shared__ float Bs3[16][68];

    int tid = threadIdx.x;
    int tx = tid & 15;   // col group: cols tx*4 .. tx*4+3
    int ty = tid >> 4;   // row group: rows ty*8 .. ty*8+7

    float acc1[8][4], acc3[8][4];
    #pragma unroll
    for (int i = 0; i < 8; i++)
        #pragma unroll
        for (int j = 0; j < 4; j++) { acc1[i][j] = 0.f; acc3[i][j] = 0.f; }

    for (int kt = 0; kt < HDIM; kt += 16) {
        __syncthreads();
        // load A tile 128x16 (512 float4, 2 per thread), store transposed
        #pragma unroll
        for (int r = 0; r < 2; r++) {
            int f = tid + r * 256;
            int row = f >> 2, kq = f & 3;
            float4 v = *(const float4*)(A + (size_t)row * HDIM + kt + kq * 4);
            As[kq * 4 + 0][row] = v.x;
            As[kq * 4 + 1][row] = v.y;
            As[kq * 4 + 2][row] = v.z;
            As[kq * 4 + 3][row] = v.w;
        }
        // load B tiles 16x64 each (256 float4, 1 per thread per matrix)
        {
            int row = tid >> 4, q = tid & 15;
            *(float4*)&Bs1[row][q * 4] = *(const float4*)(B1 + (size_t)(kt + row) * IDIM + q * 4);
            *(float4*)&Bs3[row][q * 4] = *(const float4*)(B3 + (size_t)(kt + row) * IDIM + q * 4);
        }
        __syncthreads();
        #pragma unroll
        for (int k = 0; k < 16; k++) {
            float a[8], b1[4], b3[4];
            *(float4*)&a[0] = *(float4*)&As[k][ty * 8];
            *(float4*)&a[4] = *(float4*)&As[k][ty * 8 + 4];
            *(float4*)&b1[0] = *(float4*)&Bs1[k][tx * 4];
            *(float4*)&b3[0] = *(float4*)&Bs3[k][tx * 4];
            #pragma unroll
            for (int i = 0; i < 8; i++)
                #pragma unroll
                for (int j = 0; j < 4; j++) {
                    acc1[i][j] += a[i] * b1[j];
                    acc3[i][j] += a[i] * b3[j];
                }
        }
    }

    // epilogue: h = silu(acc1) * acc3
    float* Hp = g_Hbuf + (size_t)(e * CAP + row0) * IDIM + blockIdx.x * 64;
    #pragma unroll
    for (int i = 0; i < 8; i++) {
        int row = ty * 8 + i;
        float4 h4;
        float* h = (float*)&h4;
        #pragma unroll
        for (int j = 0; j < 4; j++) {
            float x1 = acc1[i][j];
            float s  = 1.f / (1.f + expf(-x1));
            h[j] = x1 * s * acc3[i][j];
        }
        *(float4*)(Hp + (size_t)row * IDIM + tx * 4) = h4;
    }
}

// ---------------- kernel 5: GEMM2 (H @ w2) -----------------------------------
// C[128 x 128] tiles; grid.x = HDIM/128, grid.y = NE*32
__global__ __launch_bounds__(256) void gemm2_kernel(const float* __restrict__ W2) {
    int e  = blockIdx.y >> 5;
    int mt = blockIdx.y & 31;
    int cnt = g_cnt[e];
    int row0 = mt * 128;
    if (row0 >= cnt) return;

    const float* A  = g_Hbuf + (size_t)(e * CAP + row0) * IDIM;
    const float* Bm = W2 + (size_t)e * IDIM * HDIM + blockIdx.x * 128;

    __shared__ float As[16][132];
    __shared__ float Bs[16][132];

    int tid = threadIdx.x;
    int tx = tid & 15;   // cols tx*8 .. tx*8+7
    int ty = tid >> 4;   // rows ty*8 .. ty*8+7

    float acc[8][8];
    #pragma unroll
    for (int i = 0; i < 8; i++)
        #pragma unroll
        for (int j = 0; j < 8; j++) acc[i][j] = 0.f;

    for (int kt = 0; kt < IDIM; kt += 16) {
        __syncthreads();
        #pragma unroll
        for (int r = 0; r < 2; r++) {
            int f = tid + r * 256;
            int row = f >> 2, kq = f & 3;
            float4 v = *(const float4*)(A + (size_t)row * IDIM + kt + kq * 4);
            As[kq * 4 + 0][row] = v.x;
            As[kq * 4 + 1][row] = v.y;
            As[kq * 4 + 2][row] = v.z;
            As[kq * 4 + 3][row] = v.w;
        }
        #pragma unroll
        for (int r = 0; r < 2; r++) {
            int f = tid + r * 256;
            int row = f >> 5, q = f & 31;   // 16 rows x 32 float4
            *(float4*)&Bs[row][q * 4] = *(const float4*)(Bm + (size_t)(kt + row) * HDIM + q * 4);
        }
        __syncthreads();
        #pragma unroll
        for (int k = 0; k < 16; k++) {
            float a[8], b[8];
            *(float4*)&a[0] = *(float4*)&As[k][ty * 8];
            *(float4*)&a[4] = *(float4*)&As[k][ty * 8 + 4];
            *(float4*)&b[0] = *(float4*)&Bs[k][tx * 8];
            *(float4*)&b[4] = *(float4*)&Bs[k][tx * 8 + 4];
            #pragma unroll
            for (int i = 0; i < 8; i++)
                #pragma unroll
                for (int j = 0; j < 8; j++)
                    acc[i][j] += a[i] * b[j];
        }
    }

    float* Yp = g_Y + (size_t)(e * CAP + row0) * HDIM + blockIdx.x * 128;
    #pragma unroll
    for (int i = 0; i < 8; i++) {
        int row = ty * 8 + i;
        #pragma unroll
        for (int j4 = 0; j4 < 8; j4 += 4) {
            float4 v;
            v.x = acc[i][j4 + 0];
            v.y = acc[i][j4 + 1];
            v.z = acc[i][j4 + 2];
            v.w = acc[i][j4 + 3];
            *(float4*)(Yp + (size_t)row * HDIM + tx * 8 + j4) = v;
        }
    }
}

// ---------------- kernel 6: weighted combine ---------------------------------
__global__ void combine_kernel(float* __restrict__ out) {
    int t = blockIdx.x;
    int s0 = g_slotOf[2 * t], s1 = g_slotOf[2 * t + 1];
    float w0 = g_wgt[2 * t], w1 = g_wgt[2 * t + 1];
    const float4* y0 = (const float4*)(g_Y + (size_t)s0 * HDIM);
    const float4* y1 = (const float4*)(g_Y + (size_t)s1 * HDIM);
    float4 a = y0[threadIdx.x];
    float4 b = y1[threadIdx.x];
    float4 r;
    r.x = w0 * a.x + w1 * b.x;
    r.y = w0 * a.y + w1 * b.y;
    r.z = w0 * a.z + w1 * b.z;
    r.w = w0 * a.w + w1 * b.w;
    ((float4*)(out + (size_t)t * HDIM))[threadIdx.x] = r;
}

// ---------------- launcher ----------------------------------------------------
extern "C" void kernel_launch(void* const* d_in, const int* in_sizes, int n_in,
                              void* d_out, int out_size) {
    const float* X  = (const float*)d_in[0];   // [2,2048,1024]
    const float* GW = (const float*)d_in[1];   // [1024,8]
    const float* W1 = (const float*)d_in[2];   // [8,1024,4096]
    const float* W3 = (const float*)d_in[3];   // [8,1024,4096]
    const float* W2 = (const float*)d_in[4];   // [8,4096,1024]
    float* out = (float*)d_out;                      // final [4096,1024]
    float* out_logits = out + (size_t)NTOK * HDIM;   // router_logits [4096,8]

    zero_cnt_kernel<<<1, 32>>>();
    router_kernel<<<NTOK, 256>>>(X, GW, out_logits);
    scatter_kernel<<<NASSIGN / 256, 256>>>();
    gather_kernel<<<NASSIGN, 256>>>(X);
    gemm1_kernel<<<dim3(IDIM / 64, NE * 32), 256>>>(W1, W3);
    gemm2_kernel<<<dim3(HDIM / 128, NE * 32), 256>>>(W2);
    combine_kernel<<<NTOK, 256>>>(out);
}

// round 6
// speedup vs baseline: 3.8957x; 3.8957x over previous
#include <cuda_runtime.h>
#include <cuda_fp16.h>
#include <math.h>

#define NE    8
#define HDIM  1024
#define IDIM  4096
#define NTOK  4096
#define CAP   4096
#define NASSIGN (NTOK * 2)

// ---------------- scratch (static device globals; no runtime alloc) ----------
__device__ __half g_Xg[NE * CAP * HDIM];     // 67MB  gathered activations (fp16)
__device__ __half g_T1[NE * CAP * IDIM];     // 268MB X@w1 (then overwritten with H)
__device__ __half g_T3[NE * CAP * IDIM];     // 268MB X@w3
__device__ __half g_Y[NE * CAP * HDIM];      // 67MB  expert outputs
__device__ __half g_W1t[NE * HDIM * IDIM];   // 67MB  w1 transposed [E][I][H] fp16
__device__ __half g_W3t[NE * HDIM * IDIM];   // 67MB
__device__ __half g_W2t[NE * IDIM * HDIM];   // 67MB  w2 transposed [E][H][I] fp16
__device__ int   g_cnt[NE];
__device__ int   g_sel[NASSIGN];
__device__ float g_wgt[NASSIGN];
__device__ int   g_slotOf[NASSIGN];

__device__ __forceinline__ unsigned smem_u32(const void* p) {
    return (unsigned)__cvta_generic_to_shared(p);
}
#define CPA16(dst, src) asm volatile("cp.async.cg.shared.global [%0], [%1], 16;" :: "r"(dst), "l"(src))
#define CP_COMMIT()     asm volatile("cp.async.commit_group;")
#define CP_WAIT1()      asm volatile("cp.async.wait_group 1;")
#define CP_WAIT0()      asm volatile("cp.async.wait_group 0;")

// ---------------- kernel 0: zero counters ------------------------------------
__global__ void zero_cnt_kernel() {
    if (threadIdx.x < NE) g_cnt[threadIdx.x] = 0;
}

// ---------------- kernel 1: router (logits, top-2, softmax) ------------------
__global__ void router_kernel(const float* __restrict__ X,
                              const float* __restrict__ GW,
                              float* __restrict__ out_logits) {
    int t = blockIdx.x;
    int w = threadIdx.x >> 5;
    int lane = threadIdx.x & 31;
    __shared__ float slog[NE];

    const float* x = X + (size_t)t * HDIM;
    float acc = 0.f;
    for (int i = lane; i < HDIM; i += 32)
        acc += x[i] * GW[i * NE + w];
    #pragma unroll
    for (int o = 16; o > 0; o >>= 1)
        acc += __shfl_xor_sync(0xffffffffu, acc, o);
    if (lane == 0) {
        slog[w] = acc;
        out_logits[t * NE + w] = acc;
    }
    __syncthreads();

    if (threadIdx.x == 0) {
        int i0 = 0; float l0 = slog[0];
        #pragma unroll
        for (int e = 1; e < NE; e++)
            if (slog[e] > l0) { l0 = slog[e]; i0 = e; }
        int i1 = -1; float l1 = -1e30f;
        #pragma unroll
        for (int e = 0; e < NE; e++)
            if (e != i0 && slog[e] > l1) { l1 = slog[e]; i1 = e; }
        float e1 = expf(l1 - l0);
        float inv = 1.f / (1.f + e1);
        g_sel[2 * t]     = i0;  g_wgt[2 * t]     = inv;
        g_sel[2 * t + 1] = i1;  g_wgt[2 * t + 1] = e1 * inv;
    }
}

// ---------------- kernel 2: scatter ------------------------------------------
__global__ void scatter_kernel() {
    int idx = blockIdx.x * blockDim.x + threadIdx.x;
    if (idx >= NASSIGN) return;
    int e = g_sel[idx];
    int pos = atomicAdd(&g_cnt[e], 1);
    g_slotOf[idx] = e * CAP + pos;
}

// ---------------- kernel 3: gather rows, convert to fp16 ---------------------
__global__ void gather_kernel(const float* __restrict__ X) {
    int a = blockIdx.x;
    int slot = g_slotOf[a];
    int t = a >> 1;
    const float4* src = (const float4*)(X + (size_t)t * HDIM);
    __half2* dst = (__half2*)(g_Xg + (size_t)slot * HDIM);
    int i = threadIdx.x;
    float4 v = src[i];
    dst[2 * i]     = __floats2half2_rn(v.x, v.y);
    dst[2 * i + 1] = __floats2half2_rn(v.z, v.w);
}

// ---------------- kernel: convert + transpose weights ------------------------
// src: [E][R][C] fp32  ->  dst: [E][C][R] fp16
__global__ __launch_bounds__(256) void convtrans_kernel(const float* __restrict__ src,
                                                        __half* __restrict__ dst,
                                                        int R, int C) {
    __shared__ float t[32][33];
    int e = blockIdx.z;
    src += (size_t)e * R * C;
    dst += (size_t)e * R * C;
    int c0 = blockIdx.x * 32, r0 = blockIdx.y * 32;
    #pragma unroll
    for (int i = threadIdx.y; i < 32; i += 8)
        t[i][threadIdx.x] = src[(size_t)(r0 + i) * C + c0 + threadIdx.x];
    __syncthreads();
    #pragma unroll
    for (int i = threadIdx.y; i < 32; i += 8)
        dst[(size_t)(c0 + i) * R + r0 + threadIdx.x] = __float2half(t[threadIdx.x][i]);
}

// ---------------- GEMM: C[half] = A[half, MxK] @ B^T[half, NxK] --------------
// block tile 128x128, K-tile 32, 8 warps (warp tile 32x64), mma m16n8k16
// A: row-major [M][K] (K contiguous), B: [N][K] (transposed weights, K contiguous)
// C: half, row-major, ldC = Ntotal. Early-exit on dead M tiles via g_cnt.
__global__ __launch_bounds__(256, 2) void gemm_f16_kernel(
    const __half* __restrict__ A, const __half* __restrict__ B,
    __half* __restrict__ C, int K) {

    int e  = blockIdx.y >> 5;
    int mt = blockIdx.y & 31;
    int cnt = g_cnt[e];
    int row0 = mt * 128;
    if (row0 >= cnt) return;

    int N = gridDim.x * 128;
    int n0 = blockIdx.x * 128;

    const __half* Ab = A + (size_t)(e * CAP + row0) * K;
    const __half* Bb = B + (size_t)e * N * K + (size_t)n0 * K;

    __shared__ __half As[2][128][40];
    __shared__ __half Bs[2][128][40];

    int tid = threadIdx.x;
    int lane = tid & 31;
    int wid = tid >> 5;
    int wm = (wid & 3) * 32;
    int wn = (wid >> 2) * 64;
    int fr = lane >> 2;
    int fc = (lane & 3) * 2;

    float acc[2][8][4];
    #pragma unroll
    for (int mi = 0; mi < 2; mi++)
        #pragma unroll
        for (int ni = 0; ni < 8; ni++)
            #pragma unroll
            for (int j = 0; j < 4; j++) acc[mi][ni][j] = 0.f;

    // prologue: prefetch tile 0
    {
        #pragma unroll
        for (int r = 0; r < 2; r++) {
            int f = tid + r * 256;
            int row = f >> 2, kc = f & 3;
            CPA16(smem_u32(&As[0][row][kc * 8]), Ab + (size_t)row * K + kc * 8);
            CPA16(smem_u32(&Bs[0][row][kc * 8]), Bb + (size_t)row * K + kc * 8);
        }
        CP_COMMIT();
    }

    int buf = 0;
    for (int kt = 0; kt < K; kt += 32, buf ^= 1) {
        if (kt + 32 < K) {
            #pragma unroll
            for (int r = 0; r < 2; r++) {
                int f = tid + r * 256;
                int row = f >> 2, kc = f & 3;
                CPA16(smem_u32(&As[buf ^ 1][row][kc * 8]), Ab + (size_t)row * K + kt + 32 + kc * 8);
                CPA16(smem_u32(&Bs[buf ^ 1][row][kc * 8]), Bb + (size_t)row * K + kt + 32 + kc * 8);
            }
            CP_COMMIT();
            CP_WAIT1();
        } else {
            CP_WAIT0();
        }
        __syncthreads();

        #pragma unroll
        for (int ks = 0; ks < 32; ks += 16) {
            unsigned ra[2][4], rb[8][2];
            #pragma unroll
            for (int mi = 0; mi < 2; mi++) {
                const __half* ap = &As[buf][wm + mi * 16 + fr][ks + fc];
                ra[mi][0] = *(const unsigned*)ap;
                ra[mi][1] = *(const unsigned*)(ap + 8 * 40);
                ra[mi][2] = *(const unsigned*)(ap + 8);
                ra[mi][3] = *(const unsigned*)(ap + 8 * 40 + 8);
            }
            #pragma unroll
            for (int ni = 0; ni < 8; ni++) {
                const __half* bp = &Bs[buf][wn + ni * 8 + fr][ks + fc];
                rb[ni][0] = *(const unsigned*)bp;
                rb[ni][1] = *(const unsigned*)(bp + 8);
            }
            #pragma unroll
            for (int mi = 0; mi < 2; mi++)
                #pragma unroll
                for (int ni = 0; ni < 8; ni++) {
                    asm volatile(
                        "mma.sync.aligned.m16n8k16.row.col.f32.f16.f16.f32 "
                        "{%0,%1,%2,%3}, {%4,%5,%6,%7}, {%8,%9}, {%0,%1,%2,%3};"
                        : "+f"(acc[mi][ni][0]), "+f"(acc[mi][ni][1]),
                          "+f"(acc[mi][ni][2]), "+f"(acc[mi][ni][3])
                        : "r"(ra[mi][0]), "r"(ra[mi][1]), "r"(ra[mi][2]), "r"(ra[mi][3]),
                          "r"(rb[ni][0]), "r"(rb[ni][1]));
                }
        }
        __syncthreads();
    }

    // epilogue: store fp16
    __half* Cb = C + (size_t)(e * CAP + row0) * N + n0;
    #pragma unroll
    for (int mi = 0; mi < 2; mi++) {
        int r = wm + mi * 16 + fr;
        #pragma unroll
        for (int ni = 0; ni < 8; ni++) {
            int cc = wn + ni * 8 + fc;
            *(__half2*)(Cb + (size_t)r * N + cc) =
                __floats2half2_rn(acc[mi][ni][0], acc[mi][ni][1]);
            *(__half2*)(Cb + (size_t)(r + 8) * N + cc) =
                __floats2half2_rn(acc[mi][ni][2], acc[mi][ni][3]);
        }
    }
}

// ---------------- kernel: h = silu(T1) * T3 (in-place into T1) ---------------
__global__ void silu_kernel() {
    int a = blockIdx.x;
    int row = g_slotOf[a];
    __half2* p1 = (__half2*)(g_T1 + (size_t)row * IDIM);
    const __half2* p3 = (const __half2*)(g_T3 + (size_t)row * IDIM);
    #pragma unroll
    for (int j = threadIdx.x; j < IDIM / 2; j += 256) {
        float2 t1 = __half22float2(p1[j]);
        float2 t3 = __half22float2(p3[j]);
        float h0 = t1.x / (1.f + expf(-t1.x)) * t3.x;
        float h1 = t1.y / (1.f + expf(-t1.y)) * t3.y;
        p1[j] = __floats2half2_rn(h0, h1);
    }
}

// ---------------- kernel: weighted combine -----------------------------------
__global__ void combine_kernel(float* __restrict__ out) {
    int t = blockIdx.x;
    int s0 = g_slotOf[2 * t], s1 = g_slotOf[2 * t + 1];
    float w0 = g_wgt[2 * t], w1 = g_wgt[2 * t + 1];
    const __half2* y0 = (const __half2*)(g_Y + (size_t)s0 * HDIM);
    const __half2* y1 = (const __half2*)(g_Y + (size_t)s1 * HDIM);
    float2* orow = (float2*)(out + (size_t)t * HDIM);
    #pragma unroll
    for (int j = threadIdx.x; j < HDIM / 2; j += 256) {
        float2 a = __half22float2(y0[j]);
        float2 b = __half22float2(y1[j]);
        float2 r;
        r.x = w0 * a.x + w1 * b.x;
        r.y = w0 * a.y + w1 * b.y;
        orow[j] = r;
    }
}

// ---------------- launcher ----------------------------------------------------
extern "C" void kernel_launch(void* const* d_in, const int* in_sizes, int n_in,
                              void* d_out, int out_size) {
    const float* X  = (const float*)d_in[0];   // [2,2048,1024]
    const float* GW = (const float*)d_in[1];   // [1024,8]
    const float* W1 = (const float*)d_in[2];   // [8,1024,4096]
    const float* W3 = (const float*)d_in[3];   // [8,1024,4096]
    const float* W2 = (const float*)d_in[4];   // [8,4096,1024]
    float* out = (float*)d_out;
    float* out_logits = out + (size_t)NTOK * HDIM;

    __half* w1t; cudaGetSymbolAddress((void**)&w1t, g_W1t);
    __half* w3t; cudaGetSymbolAddress((void**)&w3t, g_W3t);
    __half* w2t; cudaGetSymbolAddress((void**)&w2t, g_W2t);
    __half* xg;  cudaGetSymbolAddress((void**)&xg,  g_Xg);
    __half* t1;  cudaGetSymbolAddress((void**)&t1,  g_T1);
    __half* t3;  cudaGetSymbolAddress((void**)&t3,  g_T3);
    __half* yy;  cudaGetSymbolAddress((void**)&yy,  g_Y);

    zero_cnt_kernel<<<1, 32>>>();
    router_kernel<<<NTOK, 256>>>(X, GW, out_logits);
    scatter_kernel<<<NASSIGN / 256, 256>>>();
    gather_kernel<<<NASSIGN, 256>>>(X);

    // weight convert+transpose: [E][R][C] fp32 -> [E][C][R] fp16
    convtrans_kernel<<<dim3(IDIM / 32, HDIM / 32, NE), dim3(32, 8)>>>(W1, w1t, HDIM, IDIM);
    convtrans_kernel<<<dim3(IDIM / 32, HDIM / 32, NE), dim3(32, 8)>>>(W3, w3t, HDIM, IDIM);
    convtrans_kernel<<<dim3(HDIM / 32, IDIM / 32, NE), dim3(32, 8)>>>(W2, w2t, IDIM, HDIM);

    // T1 = X@w1, T3 = X@w3   (N = 4096)
    gemm_f16_kernel<<<dim3(IDIM / 128, NE * 32), 256>>>(xg, w1t, t1, HDIM);
    gemm_f16_kernel<<<dim3(IDIM / 128, NE * 32), 256>>>(xg, w3t, t3, HDIM);
    // H = silu(T1)*T3 in-place into T1
    silu_kernel<<<NASSIGN, 256>>>();
    // Y = H@w2   (N = 1024)
    gemm_f16_kernel<<<dim3(HDIM / 128, NE * 32), 256>>>(t1, w2t, yy, IDIM);

    combine_kernel<<<NTOK, 256>>>(out);
}

// round 8
// speedup vs baseline: 4.2071x; 1.0799x over previous
#include <cuda_runtime.h>
#include <cuda_fp16.h>
#include <math.h>
#include <stdint.h>

#define NE    8
#define HDIM  1024
#define IDIM  4096
#define NTOK  4096
#define CAP   4096
#define NASSIGN (NTOK * 2)

// ---------------- scratch (static device globals) ----------------------------
__device__ __half g_Xg[NE * CAP * HDIM];               // gathered activations fp16
__device__ __half g_H [NE * CAP * IDIM];               // silu(X@w1)*(X@w3) fp16
__device__ __half g_Y [NE * CAP * HDIM];               // expert outputs fp16
__device__ __half g_Wg[NE * (IDIM / 64) * 128 * HDIM]; // fused w1/w3, 16-row groups (8 w1 + 8 w3)
__device__ __half g_W2t[NE * HDIM * IDIM];             // [E][1024][4096] w2^T (K-major)
__device__ int   g_cnt[NE];
__device__ int   g_sel[NASSIGN];
__device__ float g_wgt[NASSIGN];
__device__ int   g_slotOf[NASSIGN];

// ---------------- helpers -----------------------------------------------------
__device__ __forceinline__ unsigned smem_u32(const void* p) {
    return (unsigned)__cvta_generic_to_shared(p);
}
#define CPA16(dst, src) asm volatile("cp.async.cg.shared.global [%0], [%1], 16;" :: "r"(dst), "l"(src))
#define CP_COMMIT()     asm volatile("cp.async.commit_group;")

// ---------------- kernel 0: zero counters ------------------------------------
__global__ void zero_cnt_kernel() {
    if (threadIdx.x < NE) g_cnt[threadIdx.x] = 0;
}

// ---------------- kernel 1: router -------------------------------------------
__global__ void router_kernel(const float* __restrict__ X,
                              const float* __restrict__ GW,
                              float* __restrict__ out_logits) {
    int t = blockIdx.x;
    int w = threadIdx.x >> 5;
    int lane = threadIdx.x & 31;
    __shared__ float slog[NE];

    const float* x = X + (size_t)t * HDIM;
    float acc = 0.f;
    for (int i = lane; i < HDIM; i += 32)
        acc += x[i] * GW[i * NE + w];
    #pragma unroll
    for (int o = 16; o > 0; o >>= 1)
        acc += __shfl_xor_sync(0xffffffffu, acc, o);
    if (lane == 0) {
        slog[w] = acc;
        out_logits[t * NE + w] = acc;
    }
    __syncthreads();

    if (threadIdx.x == 0) {
        int i0 = 0; float l0 = slog[0];
        #pragma unroll
        for (int e = 1; e < NE; e++)
            if (slog[e] > l0) { l0 = slog[e]; i0 = e; }
        int i1 = -1; float l1 = -1e30f;
        #pragma unroll
        for (int e = 0; e < NE; e++)
            if (e != i0 && slog[e] > l1) { l1 = slog[e]; i1 = e; }
        float e1 = expf(l1 - l0);
        float inv = 1.f / (1.f + e1);
        g_sel[2 * t]     = i0;  g_wgt[2 * t]     = inv;
        g_sel[2 * t + 1] = i1;  g_wgt[2 * t + 1] = e1 * inv;
    }
}

// ---------------- kernel 2: scatter ------------------------------------------
__global__ void scatter_kernel() {
    int idx = blockIdx.x * blockDim.x + threadIdx.x;
    if (idx >= NASSIGN) return;
    int e = g_sel[idx];
    int pos = atomicAdd(&g_cnt[e], 1);
    g_slotOf[idx] = e * CAP + pos;
}

// ---------------- kernel 3: gather + fp16 convert ----------------------------
__global__ void gather_kernel(const float* __restrict__ X) {
    int a = blockIdx.x;
    int slot = g_slotOf[a];
    int t = a >> 1;
    const float4* src = (const float4*)(X + (size_t)t * HDIM);
    __half2* dst = (__half2*)(g_Xg + (size_t)slot * HDIM);
    int i = threadIdx.x;
    float4 v = src[i];
    dst[2 * i]     = __floats2half2_rn(v.x, v.y);
    dst[2 * i + 1] = __floats2half2_rn(v.z, v.w);
}

// -------- convert+transpose w1/w3 into fused Wg blocks ------------------------
// src [E][HDIM][IDIM] fp32. For col c: block b=c>>6, group g=(c>>3)&7, r=c&7;
// dst row j = g*16 + r + rsel (rsel=0 for w1, 8 for w3); m = (e*64+b)*128 + j
// Tile: 32 cols (i) x 64 rows (h). half2 stores along h.
__global__ __launch_bounds__(256) void convtrans_wg_kernel(const float* __restrict__ src,
                                                           __half* __restrict__ dst,
                                                           int rsel) {
    __shared__ float t[32][65];
    int e = blockIdx.z;
    src += (size_t)e * HDIM * IDIM;
    int c0 = blockIdx.x * 32, r0 = blockIdx.y * 64;
    int tx = threadIdx.x, ty = threadIdx.y;
    #pragma unroll
    for (int i = ty; i < 64; i += 8)
        t[tx][i] = src[(size_t)(r0 + i) * IDIM + c0 + tx];
    __syncthreads();
    #pragma unroll
    for (int i = ty; i < 32; i += 8) {
        int c = c0 + i;
        size_t m = (size_t)((e * 64 + (c >> 6)) * 128 + ((c >> 3) & 7) * 16 + (c & 7) + rsel);
        *(__half2*)&dst[m * HDIM + r0 + tx * 2] =
            __floats2half2_rn(t[i][tx * 2], t[i][tx * 2 + 1]);
    }
}

// -------- convert+transpose generic: src [E][R][C] fp32 -> dst [E][C][R] fp16 -
__global__ __launch_bounds__(256) void convtrans_kernel(const float* __restrict__ src,
                                                        __half* __restrict__ dst,
                                                        int R, int C) {
    __shared__ float t[32][65];
    int e = blockIdx.z;
    src += (size_t)e * R * C;
    dst += (size_t)e * R * C;
    int c0 = blockIdx.x * 32, r0 = blockIdx.y * 64;
    int tx = threadIdx.x, ty = threadIdx.y;
    #pragma unroll
    for (int i = ty; i < 64; i += 8)
        t[tx][i] = src[(size_t)(r0 + i) * C + c0 + tx];
    __syncthreads();
    #pragma unroll
    for (int i = ty; i < 32; i += 8)
        *(__half2*)&dst[(size_t)(c0 + i) * R + r0 + tx * 2] =
            __floats2half2_rn(t[i][tx * 2], t[i][tx * 2 + 1]);
}

// ---------------- GEMM (mma.sync, BM=128, BN=128 B-rows, BK=64) ---------------
// A [M][K] fp16 K-contig; B blocks of 128 rows x K (K-contig).
// FUSE=1: B rows in 16-row groups (8 w1 + 8 w3) -> thread ni even/odd = (t1,t3)
//         pair for same logical col; writes silu(t1)*t3, 64 cols/block, ld=IDIM.
// FUSE=0: plain 128 cols, ld = gridDim.x*128.
template <int FUSE>
__global__ __launch_bounds__(256, 2) void gemm_f16_kernel(
    const __half* __restrict__ A, const __half* __restrict__ Bg,
    __half* __restrict__ C, int K) {

    int e  = blockIdx.y >> 5;
    int mt = blockIdx.y & 31;
    int cnt = g_cnt[e];
    int row0 = mt * 128;
    if (row0 >= cnt) return;

    extern __shared__ __half sm[];   // [2 bufs][A:128*72 | B:128*72]
    __half* As[2] = { sm,             sm + 2 * 128 * 72 };
    __half* Bs[2] = { sm + 128 * 72,  sm + 3 * 128 * 72 };

    const __half* Ab = A + (size_t)(e * CAP + row0) * K;
    const __half* Bb = Bg + (size_t)((e * gridDim.x + blockIdx.x) * 128) * K;

    int tid = threadIdx.x;
    int lane = tid & 31;
    int wid = tid >> 5;
    int wm = (wid & 3) * 32;      // 4 warps along M
    int wn = (wid >> 2) * 64;     // 2 warps along N(B-rows)
    int fr = lane >> 2;
    int fc = (lane & 3) * 2;

    float acc[2][8][4];
    #pragma unroll
    for (int mi = 0; mi < 2; mi++)
        #pragma unroll
        for (int ni = 0; ni < 8; ni++)
            #pragma unroll
            for (int j = 0; j < 4; j++) acc[mi][ni][j] = 0.f;

    int NK = K >> 6;

    // loader lambda: K-tile i -> buffer b  (8 chunks A + 8 chunks B per thread)
    auto load_tile = [&](int i, int b) {
        const char* Asrc = (const char*)(Ab + i * 64);
        const char* Bsrc = (const char*)(Bb + i * 64);
        unsigned sa = smem_u32(As[b]);
        unsigned sb = smem_u32(Bs[b]);
        #pragma unroll
        for (int l = 0; l < 4; l++) {
            int q = tid + l * 256;
            int row = q >> 3, c = q & 7;
            unsigned off = (unsigned)(row * 144 + c * 16);
            CPA16(sa + off, Asrc + (size_t)row * K * 2 + c * 16);
            CPA16(sb + off, Bsrc + (size_t)row * K * 2 + c * 16);
        }
    };

    load_tile(0, 0);
    CP_COMMIT();

    for (int i = 0; i < NK; i++) {
        int buf = i & 1;
        if (i + 1 < NK) {
            load_tile(i + 1, buf ^ 1);
            CP_COMMIT();
            asm volatile("cp.async.wait_group 1;");
        } else {
            asm volatile("cp.async.wait_group 0;");
        }
        __syncthreads();

        #pragma unroll
        for (int ks = 0; ks < 64; ks += 16) {
            unsigned ra[2][4], rb[8][2];
            #pragma unroll
            for (int mi = 0; mi < 2; mi++) {
                const __half* ap = As[buf] + (wm + mi * 16 + fr) * 72 + ks + fc;
                ra[mi][0] = *(const unsigned*)ap;
                ra[mi][1] = *(const unsigned*)(ap + 8 * 72);
                ra[mi][2] = *(const unsigned*)(ap + 8);
                ra[mi][3] = *(const unsigned*)(ap + 8 * 72 + 8);
            }
            #pragma unroll
            for (int ni = 0; ni < 8; ni++) {
                const __half* bp = Bs[buf] + (wn + ni * 8 + fr) * 72 + ks + fc;
                rb[ni][0] = *(const unsigned*)bp;
                rb[ni][1] = *(const unsigned*)(bp + 8);
            }
            #pragma unroll
            for (int mi = 0; mi < 2; mi++)
                #pragma unroll
                for (int ni = 0; ni < 8; ni++) {
                    asm volatile(
                        "mma.sync.aligned.m16n8k16.row.col.f32.f16.f16.f32 "
                        "{%0,%1,%2,%3}, {%4,%5,%6,%7}, {%8,%9}, {%0,%1,%2,%3};"
                        : "+f"(acc[mi][ni][0]), "+f"(acc[mi][ni][1]),
                          "+f"(acc[mi][ni][2]), "+f"(acc[mi][ni][3])
                        : "r"(ra[mi][0]), "r"(ra[mi][1]), "r"(ra[mi][2]), "r"(ra[mi][3]),
                          "r"(rb[ni][0]), "r"(rb[ni][1]));
                }
        }
        __syncthreads();
    }

    // epilogue
    if (FUSE) {
        // ni even = t1, ni odd = t3 (same logical cols). group g = wn/16 + ni/2
        #pragma unroll
        for (int mi = 0; mi < 2; mi++) {
            int r = wm + mi * 16 + fr;
            __half* Crow0 = C + (size_t)(e * CAP + row0 + r) * IDIM + blockIdx.x * 64;
            __half* Crow1 = Crow0 + (size_t)8 * IDIM;
            #pragma unroll
            for (int ng = 0; ng < 4; ng++) {
                int col = (wn >> 4) * 8 + ng * 8 + fc;  // wn/16*8 = wn>>1 ... (wn=0 or 64 -> 0 or 32)
                float t10 = acc[mi][2 * ng][0],     t11 = acc[mi][2 * ng][1];
                float t30 = acc[mi][2 * ng + 1][0], t31 = acc[mi][2 * ng + 1][1];
                float h0 = t10 / (1.f + expf(-t10)) * t30;
                float h1 = t11 / (1.f + expf(-t11)) * t31;
                *(__half2*)(Crow0 + col) = __floats2half2_rn(h0, h1);
                t10 = acc[mi][2 * ng][2];     t11 = acc[mi][2 * ng][3];
                t30 = acc[mi][2 * ng + 1][2]; t31 = acc[mi][2 * ng + 1][3];
                h0 = t10 / (1.f + expf(-t10)) * t30;
                h1 = t11 / (1.f + expf(-t11)) * t31;
                *(__half2*)(Crow1 + col) = __floats2half2_rn(h0, h1);
            }
        }
    } else {
        int Ntot = gridDim.x * 128;
        #pragma unroll
        for (int mi = 0; mi < 2; mi++) {
            int r = wm + mi * 16 + fr;
            __half* Crow0 = C + (size_t)(e * CAP + row0 + r) * Ntot + blockIdx.x * 128;
            __half* Crow1 = Crow0 + (size_t)8 * Ntot;
            #pragma unroll
            for (int ni = 0; ni < 8; ni++) {
                int col = wn + ni * 8 + fc;
                *(__half2*)(Crow0 + col) = __floats2half2_rn(acc[mi][ni][0], acc[mi][ni][1]);
                *(__half2*)(Crow1 + col) = __floats2half2_rn(acc[mi][ni][2], acc[mi][ni][3]);
            }
        }
    }
}

// ---------------- kernel: weighted combine -----------------------------------
__global__ void combine_kernel(float* __restrict__ out) {
    int t = blockIdx.x;
    int s0 = g_slotOf[2 * t], s1 = g_slotOf[2 * t + 1];
    float w0 = g_wgt[2 * t], w1 = g_wgt[2 * t + 1];
    const __half2* y0 = (const __half2*)(g_Y + (size_t)s0 * HDIM);
    const __half2* y1 = (const __half2*)(g_Y + (size_t)s1 * HDIM);
    float2* orow = (float2*)(out + (size_t)t * HDIM);
    #pragma unroll
    for (int j = threadIdx.x; j < HDIM / 2; j += 256) {
        float2 a = __half22float2(y0[j]);
        float2 b = __half22float2(y1[j]);
        float2 r;
        r.x = w0 * a.x + w1 * b.x;
        r.y = w0 * a.y + w1 * b.y;
        orow[j] = r;
    }
}

// ---------------- launcher ----------------------------------------------------
extern "C" void kernel_launch(void* const* d_in, const int* in_sizes, int n_in,
                              void* d_out, int out_size) {
    const float* X  = (const float*)d_in[0];   // [2,2048,1024]
    const float* GW = (const float*)d_in[1];   // [1024,8]
    const float* W1 = (const float*)d_in[2];   // [8,1024,4096]
    const float* W3 = (const float*)d_in[3];   // [8,1024,4096]
    const float* W2 = (const float*)d_in[4];   // [8,4096,1024]
    float* out = (float*)d_out;
    float* out_logits = out + (size_t)NTOK * HDIM;

    __half* wg;  cudaGetSymbolAddress((void**)&wg,  g_Wg);
    __half* w2t; cudaGetSymbolAddress((void**)&w2t, g_W2t);
    __half* xg;  cudaGetSymbolAddress((void**)&xg,  g_Xg);
    __half* hh;  cudaGetSymbolAddress((void**)&hh,  g_H);
    __half* yy;  cudaGetSymbolAddress((void**)&yy,  g_Y);

    const int SMEM_SZ = 4 * 128 * 72 * 2;   // 73728 B
    cudaFuncSetAttribute(gemm_f16_kernel<1>, cudaFuncAttributeMaxDynamicSharedMemorySize, SMEM_SZ);
    cudaFuncSetAttribute(gemm_f16_kernel<0>, cudaFuncAttributeMaxDynamicSharedMemorySize, SMEM_SZ);

    zero_cnt_kernel<<<1, 32>>>();
    router_kernel<<<NTOK, 256>>>(X, GW, out_logits);
    scatter_kernel<<<NASSIGN / 256, 256>>>();
    gather_kernel<<<NASSIGN, 256>>>(X);

    // weight repack: fused w1/w3 blocks; w2 plain transpose
    convtrans_wg_kernel<<<dim3(IDIM / 32, HDIM / 64, NE), dim3(32, 8)>>>(W1, wg, 0);
    convtrans_wg_kernel<<<dim3(IDIM / 32, HDIM / 64, NE), dim3(32, 8)>>>(W3, wg, 8);
    convtrans_kernel<<<dim3(HDIM / 32, IDIM / 64, NE), dim3(32, 8)>>>(W2, w2t, IDIM, HDIM);

    // H = silu(X@w1) * (X@w3)   (fused)
    gemm_f16_kernel<1><<<dim3(IDIM / 64, NE * 32), 256, SMEM_SZ>>>(xg, wg, hh, HDIM);
    // Y = H @ w2
    gemm_f16_kernel<0><<<dim3(HDIM / 128, NE * 32), 256, SMEM_SZ>>>(hh, w2t, yy, IDIM);

    combine_kernel<<<NTOK, 256>>>(out);
}

// round 9
// speedup vs baseline: 6.0478x; 1.4375x over previous
#include <cuda_runtime.h>
#include <cuda_fp16.h>
#include <math.h>
#include <stdint.h>

#define NE    8
#define HDIM  1024
#define IDIM  4096
#define NTOK  4096
#define CAP   4096
#define NASSIGN (NTOK * 2)

// ---------------- scratch (static device globals) ----------------------------
__device__ __half g_Xg[NE * CAP * HDIM];   // gathered activations fp16
__device__ __half g_H [NE * CAP * IDIM];   // silu(X@w1)*(X@w3) fp16
__device__ __half g_Y [NE * CAP * HDIM];   // expert outputs fp16
__device__ int   g_cnt[NE];
__device__ int   g_sel[NASSIGN];
__device__ float g_wgt[NASSIGN];
__device__ int   g_slotOf[NASSIGN];

// ---------------- helpers -----------------------------------------------------
__device__ __forceinline__ unsigned smem_u32(const void* p) {
    return (unsigned)__cvta_generic_to_shared(p);
}
#define CPA16(dst, src) asm volatile("cp.async.cg.shared.global [%0], [%1], 16;" :: "r"(dst), "l"(src))
#define CP_COMMIT()     asm volatile("cp.async.commit_group;")

#define LDSM4(R, addr) \
    asm volatile("ldmatrix.sync.aligned.m8n8.x4.shared.b16 {%0,%1,%2,%3}, [%4];" \
        : "=r"((R)[0]), "=r"((R)[1]), "=r"((R)[2]), "=r"((R)[3]) : "r"(addr))
#define LDSM4T(r0, r1, r2, r3, addr) \
    asm volatile("ldmatrix.sync.aligned.m8n8.x4.trans.shared.b16 {%0,%1,%2,%3}, [%4];" \
        : "=r"(r0), "=r"(r1), "=r"(r2), "=r"(r3) : "r"(addr))

// ---------------- kernel 0: zero counters ------------------------------------
__global__ void zero_cnt_kernel() {
    if (threadIdx.x < NE) g_cnt[threadIdx.x] = 0;
}

// ---------------- kernel 1: router -------------------------------------------
__global__ void router_kernel(const float* __restrict__ X,
                              const float* __restrict__ GW,
                              float* __restrict__ out_logits) {
    int t = blockIdx.x;
    int w = threadIdx.x >> 5;
    int lane = threadIdx.x & 31;
    __shared__ float slog[NE];

    const float* x = X + (size_t)t * HDIM;
    float acc = 0.f;
    for (int i = lane; i < HDIM; i += 32)
        acc += x[i] * GW[i * NE + w];
    #pragma unroll
    for (int o = 16; o > 0; o >>= 1)
        acc += __shfl_xor_sync(0xffffffffu, acc, o);
    if (lane == 0) {
        slog[w] = acc;
        out_logits[t * NE + w] = acc;
    }
    __syncthreads();

    if (threadIdx.x == 0) {
        int i0 = 0; float l0 = slog[0];
        #pragma unroll
        for (int e = 1; e < NE; e++)
            if (slog[e] > l0) { l0 = slog[e]; i0 = e; }
        int i1 = -1; float l1 = -1e30f;
        #pragma unroll
        for (int e = 0; e < NE; e++)
            if (e != i0 && slog[e] > l1) { l1 = slog[e]; i1 = e; }
        float e1 = expf(l1 - l0);
        float inv = 1.f / (1.f + e1);
        g_sel[2 * t]     = i0;  g_wgt[2 * t]     = inv;
        g_sel[2 * t + 1] = i1;  g_wgt[2 * t + 1] = e1 * inv;
    }
}

// ---------------- kernel 2: scatter ------------------------------------------
__global__ void scatter_kernel() {
    int idx = blockIdx.x * blockDim.x + threadIdx.x;
    if (idx >= NASSIGN) return;
    int e = g_sel[idx];
    int pos = atomicAdd(&g_cnt[e], 1);
    g_slotOf[idx] = e * CAP + pos;
}

// ---------------- kernel 3: gather + fp16 convert ----------------------------
__global__ void gather_kernel(const float* __restrict__ X) {
    int a = blockIdx.x;
    int slot = g_slotOf[a];
    int t = a >> 1;
    const float4* src = (const float4*)(X + (size_t)t * HDIM);
    __half2* dst = (__half2*)(g_Xg + (size_t)slot * HDIM);
    int i = threadIdx.x;
    float4 v = src[i];
    dst[2 * i]     = __floats2half2_rn(v.x, v.y);
    dst[2 * i + 1] = __floats2half2_rn(v.z, v.w);
}

// ---------------- GEMM (mma.sync + ldmatrix, direct fp32 weights) ------------
// A [rows][K] fp16 K-contig (g_Xg or g_H). Weights fp32, [K][n] n-contiguous
// (w1/w3: [HDIM][IDIM]; w2: [IDIM][HDIM]) — converted to fp16 SMEM in-loader.
// BM=128, BN=128, BK=32. 8 warps: 4 along M (32 rows), 2 along N (64 n').
// FUSE=1: n' interleave per 16: 8 w1-cols then matching 8 w3-cols -> a thread's
//         ni even/odd = (t1,t3) for same logical col; writes silu(t1)*t3.
// FUSE=0: plain 128 cols, ld = gridDim.x*128.
template <int FUSE>
__global__ __launch_bounds__(256, 2) void gemm_f16_kernel(
    const __half* __restrict__ A, const float* __restrict__ Wa,
    const float* __restrict__ Wb, __half* __restrict__ C, int K) {

    int e  = blockIdx.y >> 5;
    int mt = blockIdx.y & 31;
    int cnt = g_cnt[e];
    int row0 = mt * 128;
    if (row0 >= cnt) return;

    __shared__ __half As_[2][128 * 40];   // row stride 40 halves (80B)
    __shared__ __half Bs_[2][32 * 136];   // row stride 136 halves (272B)

    const __half* Ab = A + (size_t)(e * CAP + row0) * K;
    const float* Wp1;
    const float* Wp3 = nullptr;
    if (FUSE) {
        Wp1 = Wa + (size_t)e * HDIM * IDIM + blockIdx.x * 64;
        Wp3 = Wb + (size_t)e * HDIM * IDIM + blockIdx.x * 64;
    } else {
        Wp1 = Wa + (size_t)e * IDIM * HDIM + blockIdx.x * 128;
    }

    int tid = threadIdx.x;
    int lane = tid & 31;
    int wid = tid >> 5;
    int wm = (wid & 3) * 32;
    int wn = (wid >> 2) * 64;
    int fr = lane >> 2;
    int fc = (lane & 3) * 2;
    int lrow  = (lane & 7) + ((lane >> 3) & 1) * 8;   // ldmatrix row within 16
    int lcol8 = (lane >> 4) * 8;                      // ldmatrix 8-col select

    float acc[2][8][4];
    #pragma unroll
    for (int mi = 0; mi < 2; mi++)
        #pragma unroll
        for (int ni = 0; ni < 8; ni++)
            #pragma unroll
            for (int j = 0; j < 4; j++) acc[mi][ni][j] = 0.f;

    float4 stage[4];

    // ---- B: gmem fp32 -> staging regs ----
    auto ldgB = [&](int kt) {
        if (FUSE) {
            #pragma unroll
            for (int l = 0; l < 2; l++) {
                int q = tid + l * 256, k = q >> 4, c4 = q & 15;
                stage[l]     = *(const float4*)(Wp1 + (size_t)(kt + k) * IDIM + c4 * 4);
                stage[l + 2] = *(const float4*)(Wp3 + (size_t)(kt + k) * IDIM + c4 * 4);
            }
        } else {
            #pragma unroll
            for (int l = 0; l < 4; l++) {
                int q = tid + l * 256, k = q >> 5, c4 = q & 31;
                stage[l] = *(const float4*)(Wp1 + (size_t)(kt + k) * HDIM + c4 * 4);
            }
        }
    };
    // ---- B: staging regs -> fp16 smem [k][n'] ----
    auto stsB = [&](int buf) {
        __half* B = Bs_[buf];
        if (FUSE) {
            #pragma unroll
            for (int l = 0; l < 2; l++) {
                int q = tid + l * 256, k = q >> 4, c4 = q & 15;
                int n = (c4 >> 1) * 16 + (c4 & 1) * 4;
                float4 v = stage[l];
                __half2 h0 = __floats2half2_rn(v.x, v.y);
                __half2 h1 = __floats2half2_rn(v.z, v.w);
                uint2 u; u.x = *(unsigned*)&h0; u.y = *(unsigned*)&h1;
                *(uint2*)(B + k * 136 + n) = u;
                v = stage[l + 2];
                h0 = __floats2half2_rn(v.x, v.y);
                h1 = __floats2half2_rn(v.z, v.w);
                u.x = *(unsigned*)&h0; u.y = *(unsigned*)&h1;
                *(uint2*)(B + k * 136 + n + 8) = u;
            }
        } else {
            #pragma unroll
            for (int l = 0; l < 4; l++) {
                int q = tid + l * 256, k = q >> 5, c4 = q & 31;
                float4 v = stage[l];
                __half2 h0 = __floats2half2_rn(v.x, v.y);
                __half2 h1 = __floats2half2_rn(v.z, v.w);
                uint2 u; u.x = *(unsigned*)&h0; u.y = *(unsigned*)&h1;
                *(uint2*)(B + k * 136 + c4 * 4) = u;
            }
        }
    };
    // ---- A: cp.async fp16 [m][k] tile ----
    auto ldA = [&](int kt, int buf) {
        unsigned sa = smem_u32(As_[buf]);
        const char* Asrc = (const char*)(Ab + kt);
        #pragma unroll
        for (int l = 0; l < 2; l++) {
            int q = tid + l * 256, row = q >> 2, c = q & 3;
            CPA16(sa + (unsigned)(row * 80 + c * 16), Asrc + (size_t)row * K * 2 + c * 16);
        }
    };

    // prologue
    ldgB(0);
    ldA(0, 0);
    CP_COMMIT();

    int NK = K >> 5;
    for (int i = 0; i < NK; i++) {
        int buf = i & 1;
        stsB(buf);
        if (i + 1 < NK) ldgB((i + 1) * 32);
        asm volatile("cp.async.wait_group 0;");
        __syncthreads();
        if (i + 1 < NK) { ldA((i + 1) * 32, buf ^ 1); CP_COMMIT(); }

        unsigned aBase = smem_u32(As_[buf]) + (unsigned)(((wm + lrow) * 40 + lcol8) * 2);
        unsigned bBase = smem_u32(Bs_[buf]) + (unsigned)(lrow * 272 + (wn + lcol8) * 2);

        #pragma unroll
        for (int ks = 0; ks < 32; ks += 16) {
            unsigned a[2][4], b[8][2];
            LDSM4(a[0], aBase + ks * 2);
            LDSM4(a[1], aBase + 16 * 80 + ks * 2);
            #pragma unroll
            for (int p = 0; p < 4; p++)
                LDSM4T(b[2 * p][0], b[2 * p][1], b[2 * p + 1][0], b[2 * p + 1][1],
                       bBase + ks * 272 + p * 32);
            #pragma unroll
            for (int mi = 0; mi < 2; mi++)
                #pragma unroll
                for (int ni = 0; ni < 8; ni++) {
                    asm volatile(
                        "mma.sync.aligned.m16n8k16.row.col.f32.f16.f16.f32 "
                        "{%0,%1,%2,%3}, {%4,%5,%6,%7}, {%8,%9}, {%0,%1,%2,%3};"
                        : "+f"(acc[mi][ni][0]), "+f"(acc[mi][ni][1]),
                          "+f"(acc[mi][ni][2]), "+f"(acc[mi][ni][3])
                        : "r"(a[mi][0]), "r"(a[mi][1]), "r"(a[mi][2]), "r"(a[mi][3]),
                          "r"(b[ni][0]), "r"(b[ni][1]));
                }
        }
    }

    // epilogue
    if (FUSE) {
        #pragma unroll
        for (int mi = 0; mi < 2; mi++) {
            int r = wm + mi * 16 + fr;
            __half* Crow0 = C + (size_t)(e * CAP + row0 + r) * IDIM + blockIdx.x * 64;
            __half* Crow1 = Crow0 + (size_t)8 * IDIM;
            #pragma unroll
            for (int ng = 0; ng < 4; ng++) {
                int col = (wn >> 4) * 8 + ng * 8 + fc;
                float t10 = acc[mi][2 * ng][0],     t11 = acc[mi][2 * ng][1];
                float t30 = acc[mi][2 * ng + 1][0], t31 = acc[mi][2 * ng + 1][1];
                float h0 = t10 / (1.f + expf(-t10)) * t30;
                float h1 = t11 / (1.f + expf(-t11)) * t31;
                *(__half2*)(Crow0 + col) = __floats2half2_rn(h0, h1);
                t10 = acc[mi][2 * ng][2];     t11 = acc[mi][2 * ng][3];
                t30 = acc[mi][2 * ng + 1][2]; t31 = acc[mi][2 * ng + 1][3];
                h0 = t10 / (1.f + expf(-t10)) * t30;
                h1 = t11 / (1.f + expf(-t11)) * t31;
                *(__half2*)(Crow1 + col) = __floats2half2_rn(h0, h1);
            }
        }
    } else {
        int Ntot = gridDim.x * 128;
        #pragma unroll
        for (int mi = 0; mi < 2; mi++) {
            int r = wm + mi * 16 + fr;
            __half* Crow0 = C + (size_t)(e * CAP + row0 + r) * Ntot + blockIdx.x * 128;
            __half* Crow1 = Crow0 + (size_t)8 * Ntot;
            #pragma unroll
            for (int ni = 0; ni < 8; ni++) {
                int col = wn + ni * 8 + fc;
                *(__half2*)(Crow0 + col) = __floats2half2_rn(acc[mi][ni][0], acc[mi][ni][1]);
                *(__half2*)(Crow1 + col) = __floats2half2_rn(acc[mi][ni][2], acc[mi][ni][3]);
            }
        }
    }
}

// ---------------- kernel: weighted combine -----------------------------------
__global__ void combine_kernel(float* __restrict__ out) {
    int t = blockIdx.x;
    int s0 = g_slotOf[2 * t], s1 = g_slotOf[2 * t + 1];
    float w0 = g_wgt[2 * t], w1 = g_wgt[2 * t + 1];
    const __half2* y0 = (const __half2*)(g_Y + (size_t)s0 * HDIM);
    const __half2* y1 = (const __half2*)(g_Y + (size_t)s1 * HDIM);
    float2* orow = (float2*)(out + (size_t)t * HDIM);
    #pragma unroll
    for (int j = threadIdx.x; j < HDIM / 2; j += 256) {
        float2 a = __half22float2(y0[j]);
        float2 b = __half22float2(y1[j]);
        float2 r;
        r.x = w0 * a.x + w1 * b.x;
        r.y = w0 * a.y + w1 * b.y;
        orow[j] = r;
    }
}

// ---------------- launcher ----------------------------------------------------
extern "C" void kernel_launch(void* const* d_in, const int* in_sizes, int n_in,
                              void* d_out, int out_size) {
    const float* X  = (const float*)d_in[0];   // [2,2048,1024]
    const float* GW = (const float*)d_in[1];   // [1024,8]
    const float* W1 = (const float*)d_in[2];   // [8,1024,4096]
    const float* W3 = (const float*)d_in[3];   // [8,1024,4096]
    const float* W2 = (const float*)d_in[4];   // [8,4096,1024]
    float* out = (float*)d_out;
    float* out_logits = out + (size_t)NTOK * HDIM;

    __half* xg;  cudaGetSymbolAddress((void**)&xg,  g_Xg);
    __half* hh;  cudaGetSymbolAddress((void**)&hh,  g_H);
    __half* yy;  cudaGetSymbolAddress((void**)&yy,  g_Y);

    zero_cnt_kernel<<<1, 32>>>();
    router_kernel<<<NTOK, 256>>>(X, GW, out_logits);
    scatter_kernel<<<NASSIGN / 256, 256>>>();
    gather_kernel<<<NASSIGN, 256>>>(X);

    // H = silu(X@w1) * (X@w3)   (fused, fp32 weights consumed directly)
    gemm_f16_kernel<1><<<dim3(IDIM / 64, NE * 32), 256>>>(xg, W1, W3, hh, HDIM);
    // Y = H @ w2
    gemm_f16_kernel<0><<<dim3(HDIM / 128, NE * 32), 256>>>(hh, W2, nullptr, yy, IDIM);

    combine_kernel<<<NTOK, 256>>>(out);
}